// round 2
// baseline (speedup 1.0000x reference)
#include <cuda_runtime.h>
#include <math.h>

#define DM    1024
#define DI    2048
#define HD    64
#define NH    32
#define DS    128
#define DCONV 4
#define CDIM  (DI + 2*DS)         // 2304
#define DIP   (2*DI + 2*DS + NH)  // 4384
#define BSZ   4
#define LSEQ  1024
#define TOK   (BSZ*LSEQ)          // 4096
#define EPSV  1e-5f

// ---------------- scratch (static device globals; no allocations) ----------
__device__ float g_h[(size_t)TOK*DM];          // layernormed input
__device__ float g_zx[(size_t)TOK*DIP];        // in_proj output (shared by both dirs)
__device__ float g_xc[2][(size_t)TOK*DI];      // conv+silu x, per dir (dir-domain)
__device__ float g_Bc[2][(size_t)TOK*DS];
__device__ float g_Cc[2][(size_t)TOK*DS];
__device__ float g_dt[2][(size_t)TOK*NH];
__device__ float g_dA[2][(size_t)TOK*NH];
__device__ float g_y [2][(size_t)TOK*DI];      // scan out (+D*x), then gated+rmsnormed in place
__device__ float g_comb[(size_t)TOK*DI];       // combined gated activations
__device__ float g_o[(size_t)TOK*DM];          // pre-final-LN output
__device__ int   g_pos[TOK];                   // smart_flip permutation (per batch row)

// ---------------- helpers ---------------------------------------------------
__device__ __forceinline__ float block_sum(float v) {
    __shared__ float sh[33];
    int lane = threadIdx.x & 31, w = threadIdx.x >> 5;
    #pragma unroll
    for (int o = 16; o > 0; o >>= 1) v += __shfl_xor_sync(0xffffffffu, v, o);
    if (lane == 0) sh[w] = v;
    __syncthreads();
    if (threadIdx.x == 0) {
        float t = 0.f;
        int nw = blockDim.x >> 5;
        for (int i = 0; i < nw; i++) t += sh[i];
        sh[32] = t;
    }
    __syncthreads();
    float r = sh[32];
    __syncthreads();   // protect reuse across repeated calls
    return r;
}

__device__ __forceinline__ float siluf(float x) {
    return x / (1.f + expf(-x));
}

// ---------------- flip permutation ------------------------------------------
__global__ void pos_kernel(const unsigned char* __restrict__ mask) {
    int b = blockIdx.x;
    float cnt = 0.f;
    for (int i = threadIdx.x; i < LSEQ; i += blockDim.x)
        cnt += (mask[b*LSEQ + i] == 0) ? 1.f : 0.f;
    float total = block_sum(cnt);
    int len = (int)(total + 0.5f);
    for (int i = threadIdx.x; i < LSEQ; i += blockDim.x)
        g_pos[b*LSEQ + i] = (i < len) ? (len - 1 - i) : i;
}

// ---------------- layernorms --------------------------------------------------
__global__ void ln_in_kernel(const float* __restrict__ in) {
    int row = blockIdx.x;
    const float* x = in + (size_t)row * DM;
    float s = 0.f, s2 = 0.f;
    for (int i = threadIdx.x; i < DM; i += blockDim.x) {
        float v = x[i]; s += v; s2 += v*v;
    }
    float sum  = block_sum(s);
    float sums = block_sum(s2);
    float mu = sum / DM;
    float var = sums / DM - mu*mu;
    float rs = rsqrtf(var + EPSV);
    float* o = g_h + (size_t)row * DM;
    for (int i = threadIdx.x; i < DM; i += blockDim.x)
        o[i] = (x[i] - mu) * rs;
}

__global__ void ln_out_kernel(float* __restrict__ out) {
    int row = blockIdx.x;
    const float* x = g_o + (size_t)row * DM;
    float s = 0.f, s2 = 0.f;
    for (int i = threadIdx.x; i < DM; i += blockDim.x) {
        float v = x[i]; s += v; s2 += v*v;
    }
    float sum  = block_sum(s);
    float sums = block_sum(s2);
    float mu = sum / DM;
    float var = sums / DM - mu*mu;
    float rs = rsqrtf(var + EPSV);
    float* o = out + (size_t)row * DM;
    for (int i = threadIdx.x; i < DM; i += blockDim.x)
        o[i] = (x[i] - mu) * rs;
}

// ---------------- SGEMM (NT: A[M,K] row-major, B[N,K] row-major, C[M,N]) -----
// 128x128 block tile, BK=8, 256 threads, 8x8 micro-tile.
__device__ __forceinline__ void sgemm_body(const float* __restrict__ A,
                                           const float* __restrict__ Bm,
                                           float* __restrict__ C,
                                           int N, int K) {
    __shared__ float sA[8][128];
    __shared__ float sB[8][128];
    int tid = threadIdx.x;
    int m0 = blockIdx.y * 128, n0 = blockIdx.x * 128;
    int lrow = tid >> 1;
    int lk4  = (tid & 1) * 4;
    const float* Ap = A + (size_t)(m0 + lrow) * K + lk4;
    const float* Bp = Bm + (size_t)(n0 + lrow) * K + lk4;
    bool bvalid = (n0 + lrow) < N;
    int tx = tid & 15, ty = tid >> 4;

    float acc[8][8];
    #pragma unroll
    for (int i = 0; i < 8; i++)
        #pragma unroll
        for (int j = 0; j < 8; j++) acc[i][j] = 0.f;

    for (int k0 = 0; k0 < K; k0 += 8) {
        float4 av = *(const float4*)(Ap + k0);
        float4 bv = bvalid ? *(const float4*)(Bp + k0) : make_float4(0.f,0.f,0.f,0.f);
        __syncthreads();
        sA[lk4+0][lrow] = av.x; sA[lk4+1][lrow] = av.y;
        sA[lk4+2][lrow] = av.z; sA[lk4+3][lrow] = av.w;
        sB[lk4+0][lrow] = bv.x; sB[lk4+1][lrow] = bv.y;
        sB[lk4+2][lrow] = bv.z; sB[lk4+3][lrow] = bv.w;
        __syncthreads();
        #pragma unroll
        for (int kk = 0; kk < 8; kk++) {
            float a[8], b[8];
            float4 a0 = *(const float4*)&sA[kk][ty*8];
            float4 a1 = *(const float4*)&sA[kk][ty*8+4];
            float4 b0 = *(const float4*)&sB[kk][tx*8];
            float4 b1 = *(const float4*)&sB[kk][tx*8+4];
            a[0]=a0.x; a[1]=a0.y; a[2]=a0.z; a[3]=a0.w;
            a[4]=a1.x; a[5]=a1.y; a[6]=a1.z; a[7]=a1.w;
            b[0]=b0.x; b[1]=b0.y; b[2]=b0.z; b[3]=b0.w;
            b[4]=b1.x; b[5]=b1.y; b[6]=b1.z; b[7]=b1.w;
            #pragma unroll
            for (int i = 0; i < 8; i++)
                #pragma unroll
                for (int j = 0; j < 8; j++)
                    acc[i][j] = fmaf(a[i], b[j], acc[i][j]);
        }
    }
    #pragma unroll
    for (int i = 0; i < 8; i++) {
        int row = m0 + ty*8 + i;
        float* cr = C + (size_t)row * N;
        #pragma unroll
        for (int j = 0; j < 8; j++) {
            int col = n0 + tx*8 + j;
            if (col < N) cr[col] = acc[i][j];
        }
    }
}

__global__ void __launch_bounds__(256) gemm1_kernel(const float* __restrict__ W) {
    sgemm_body(g_h, W, g_zx, DIP, DM);      // [4096,1024] x [4384,1024]^T
}
__global__ void __launch_bounds__(256) gemm2_kernel(const float* __restrict__ W) {
    sgemm_body(g_comb, W, g_o, DM, DI);     // [4096,2048] x [1024,2048]^T
}

// ---------------- causal depthwise conv + silu + split + dt/dA --------------
__global__ void conv_kernel(const float* __restrict__ cw_f, const float* __restrict__ cb_f,
                            const float* __restrict__ cw_r, const float* __restrict__ cb_r,
                            const float* __restrict__ dtb_f, const float* __restrict__ Al_f,
                            const float* __restrict__ dtb_r, const float* __restrict__ Al_r) {
    int t   = blockIdx.x;               // token in this direction's domain
    int dir = blockIdx.y;
    int b = t / LSEQ, lp = t % LSEQ;
    const float* cw = dir ? cw_r : cw_f;
    const float* cb = dir ? cb_r : cb_f;

    int rows[4];
    #pragma unroll
    for (int k = 0; k < 4; k++) {
        int j = lp + k - 3;
        rows[k] = (j >= 0) ? (b*LSEQ + (dir ? g_pos[b*LSEQ + j] : j)) : -1;
    }

    for (int c = threadIdx.x; c < CDIM; c += blockDim.x) {
        float acc = cb[c];
        #pragma unroll
        for (int k = 0; k < 4; k++) {
            if (rows[k] >= 0)
                acc = fmaf(cw[c*DCONV + k], g_zx[(size_t)rows[k]*DIP + DI + c], acc);
        }
        float v = siluf(acc);
        if (c < DI)            g_xc[dir][(size_t)t*DI + c] = v;
        else if (c < DI + DS)  g_Bc[dir][(size_t)t*DS + (c - DI)] = v;
        else                   g_Cc[dir][(size_t)t*DS + (c - DI - DS)] = v;
    }

    if (threadIdx.x < NH) {
        int hh = threadIdx.x;
        int srow = b*LSEQ + (dir ? g_pos[t] : lp);
        float dtr = g_zx[(size_t)srow*DIP + DI + CDIM + hh] + (dir ? dtb_r : dtb_f)[hh];
        float dtv = (dtr > 20.f) ? dtr : log1pf(expf(dtr));
        float A = -expf((dir ? Al_r : Al_f)[hh]);
        g_dt[dir][(size_t)t*NH + hh] = dtv;
        g_dA[dir][(size_t)t*NH + hh] = expf(dtv * A);
    }
}

// ---------------- selective scan ---------------------------------------------
#define CH 16
__global__ void __launch_bounds__(512) scan_kernel(const float* __restrict__ Df,
                                                   const float* __restrict__ Dr) {
    int bh  = blockIdx.x;               // b*NH + head
    int dir = blockIdx.y;
    int b = bh / NH, hd = bh % NH;
    int tid = threadIdx.x;
    int p = tid >> 3, sub = tid & 7, nb = sub * 16;
    float Dv = (dir ? Dr : Df)[hd];

    __shared__ float sB[CH][DS], sC[CH][DS], sx[CH][HD];
    __shared__ float sdt[CH], sdA[CH];

    float h[16];
    #pragma unroll
    for (int i = 0; i < 16; i++) h[i] = 0.f;

    const float* Bg  = g_Bc[dir] + (size_t)b*LSEQ*DS;
    const float* Cg  = g_Cc[dir] + (size_t)b*LSEQ*DS;
    const float* xg  = g_xc[dir] + (size_t)b*LSEQ*DI + hd*HD;
    const float* dtg = g_dt[dir] + (size_t)b*LSEQ*NH + hd;
    const float* dAg = g_dA[dir] + (size_t)b*LSEQ*NH + hd;
    float* yg        = g_y[dir]  + (size_t)b*LSEQ*DI + hd*HD;

    for (int l0 = 0; l0 < LSEQ; l0 += CH) {
        #pragma unroll
        for (int r = 0; r < 4; r++) {                 // CH*DS = 2048 floats
            int e = r*512 + tid;
            int s = e >> 7, n = e & 127;
            sB[s][n] = Bg[(size_t)(l0+s)*DS + n];
            sC[s][n] = Cg[(size_t)(l0+s)*DS + n];
        }
        #pragma unroll
        for (int r = 0; r < 2; r++) {                 // CH*HD = 1024 floats
            int e = r*512 + tid;
            int s = e >> 6, pp = e & 63;
            sx[s][pp] = xg[(size_t)(l0+s)*DI + pp];
        }
        if (tid < CH) {
            sdt[tid] = dtg[(size_t)(l0+tid)*NH];
            sdA[tid] = dAg[(size_t)(l0+tid)*NH];
        }
        __syncthreads();

        #pragma unroll
        for (int s = 0; s < CH; s++) {
            float xv  = sx[s][p];
            float kf  = sdt[s] * xv;
            float dAv = sdA[s];
            float yp = 0.f;
            const float4* Bv = (const float4*)&sB[s][nb];
            const float4* Cv = (const float4*)&sC[s][nb];
            #pragma unroll
            for (int q = 0; q < 4; q++) {
                float4 bq = Bv[q], cq = Cv[q];
                h[q*4+0] = fmaf(h[q*4+0], dAv, kf*bq.x); yp = fmaf(h[q*4+0], cq.x, yp);
                h[q*4+1] = fmaf(h[q*4+1], dAv, kf*bq.y); yp = fmaf(h[q*4+1], cq.y, yp);
                h[q*4+2] = fmaf(h[q*4+2], dAv, kf*bq.z); yp = fmaf(h[q*4+2], cq.z, yp);
                h[q*4+3] = fmaf(h[q*4+3], dAv, kf*bq.w); yp = fmaf(h[q*4+3], cq.w, yp);
            }
            yp += __shfl_xor_sync(0xffffffffu, yp, 1);
            yp += __shfl_xor_sync(0xffffffffu, yp, 2);
            yp += __shfl_xor_sync(0xffffffffu, yp, 4);
            if (sub == 0)
                yg[(size_t)(l0+s)*DI + p] = fmaf(Dv, xv, yp);
        }
        __syncthreads();
    }
}

// ---------------- gating + RMSNorm (in place on g_y) -------------------------
__global__ void gate_kernel(const float* __restrict__ nwf, const float* __restrict__ nwr) {
    int t = blockIdx.x, dir = blockIdx.y;
    int b = t / LSEQ, lp = t % LSEQ;
    int ztok = b*LSEQ + (dir ? g_pos[t] : lp);
    const float* nw = dir ? nwr : nwf;
    float* y = g_y[dir] + (size_t)t*DI;
    const float* z = g_zx + (size_t)ztok*DIP;

    float gv[8];
    float s2 = 0.f;
    #pragma unroll
    for (int r = 0; r < 8; r++) {
        int c = r*256 + threadIdx.x;
        float zv = z[c];
        float g = y[c] * siluf(zv);
        gv[r] = g;
        s2 = fmaf(g, g, s2);
    }
    float total = block_sum(s2);
    float sc = rsqrtf(total / DI + EPSV);
    #pragma unroll
    for (int r = 0; r < 8; r++) {
        int c = r*256 + threadIdx.x;
        y[c] = gv[r] * sc * nw[c];
    }
}

// ---------------- combine forward + flipped reverse --------------------------
__global__ void combine_kernel() {
    int t = blockIdx.x;
    int b = t / LSEQ;
    int rt = b*LSEQ + g_pos[t];
    const float* yf = g_y[0] + (size_t)t*DI;
    const float* yr = g_y[1] + (size_t)rt*DI;
    float* o = g_comb + (size_t)t*DI;
    for (int c = threadIdx.x; c < DI; c += blockDim.x)
        o[c] = 0.5f * (yf[c] + yr[c]);
}

// ---------------- launch ------------------------------------------------------
extern "C" void kernel_launch(void* const* d_in, const int* in_sizes, int n_in,
                              void* d_out, int out_size) {
    const float* hidden  = (const float*)d_in[0];
    const unsigned char* mask = (const unsigned char*)d_in[1];
    const float* in_proj = (const float*)d_in[2];
    const float* out_proj= (const float*)d_in[3];
    const float* cw_f  = (const float*)d_in[4];
    const float* cb_f  = (const float*)d_in[5];
    const float* dtb_f = (const float*)d_in[6];
    const float* Al_f  = (const float*)d_in[7];
    const float* D_f   = (const float*)d_in[8];
    const float* nw_f  = (const float*)d_in[9];
    const float* cw_r  = (const float*)d_in[10];
    const float* cb_r  = (const float*)d_in[11];
    const float* dtb_r = (const float*)d_in[12];
    const float* Al_r  = (const float*)d_in[13];
    const float* D_r   = (const float*)d_in[14];
    const float* nw_r  = (const float*)d_in[15];
    float* out = (float*)d_out;

    pos_kernel<<<BSZ, 256>>>(mask);
    ln_in_kernel<<<TOK, 256>>>(hidden);
    gemm1_kernel<<<dim3((DIP + 127)/128, TOK/128), 256>>>(in_proj);
    conv_kernel<<<dim3(TOK, 2), 256>>>(cw_f, cb_f, cw_r, cb_r, dtb_f, Al_f, dtb_r, Al_r);
    scan_kernel<<<dim3(BSZ*NH, 2), 512>>>(D_f, D_r);
    gate_kernel<<<dim3(TOK, 2), 256>>>(nw_f, nw_r);
    combine_kernel<<<TOK, 256>>>();
    gemm2_kernel<<<dim3(DM/128, TOK/128), 256>>>(out_proj);
    ln_out_kernel<<<TOK, 256>>>(out);
}

// round 4
// speedup vs baseline: 1.3286x; 1.3286x over previous
#include <cuda_runtime.h>
#include <math.h>
#include <stdint.h>

#define DM    1024
#define DI    2048
#define HD    64
#define NH    32
#define DS    128
#define DCONV 4
#define CDIM  (DI + 2*DS)         // 2304
#define DIP   (2*DI + 2*DS + NH)  // 4384
#define DIPP  4480                // DIP padded to 128-multiple for GEMM1
#define BSZ   4
#define LSEQ  1024
#define TOK   (BSZ*LSEQ)          // 4096
#define EPSV  1e-5f

// ---------------- scratch (static device globals; no allocations) ----------
__device__ float g_h[(size_t)TOK*DM];           // layernormed input (tf32-rounded)
__device__ float g_zx[(size_t)TOK*DIPP];        // in_proj output (padded stride)
__device__ float g_xc[2][(size_t)TOK*DI];
__device__ float g_Bc[2][(size_t)TOK*DS];
__device__ float g_Cc[2][(size_t)TOK*DS];
__device__ float g_dt[2][(size_t)TOK*NH];
__device__ float g_dA[2][(size_t)TOK*NH];
__device__ float g_y [2][(size_t)TOK*DI];
__device__ float g_comb[(size_t)TOK*DI];        // combined (tf32-rounded)
__device__ float g_o[(size_t)TOK*DM];
__device__ int   g_pos[TOK];
__device__ float g_w1t[(size_t)DIPP*DM];        // in_proj tf32-rounded, row-padded
__device__ float g_w2t[(size_t)DM*DI];          // out_proj tf32-rounded

// ---------------- small asm helpers -----------------------------------------
__device__ __forceinline__ uint32_t smem_u32(const void* p) {
    uint32_t a;
    asm("{ .reg .u64 t; cvta.to.shared.u64 t, %1; cvt.u32.u64 %0, t; }" : "=r"(a) : "l"(p));
    return a;
}
__device__ __forceinline__ void cp16(uint32_t dst, const void* src) {
    asm volatile("cp.async.cg.shared.global [%0], [%1], 16;" :: "r"(dst), "l"(src) : "memory");
}
#define CP_COMMIT() asm volatile("cp.async.commit_group;" ::: "memory")
#define CP_WAIT2()  asm volatile("cp.async.wait_group 2;" ::: "memory")

__device__ __forceinline__ uint32_t sw128(uint32_t off) { return off ^ ((off >> 3) & 0x70); }

__device__ __forceinline__ float rna_tf32(float x) {
    uint32_t u;
    asm("cvt.rna.tf32.f32 %0, %1;" : "=r"(u) : "f"(x));
    return __uint_as_float(u);
}

__device__ __forceinline__ void ldsm4(uint32_t& r0, uint32_t& r1, uint32_t& r2, uint32_t& r3,
                                      uint32_t addr) {
    asm volatile("ldmatrix.sync.aligned.m8n8.x4.shared.b16 {%0,%1,%2,%3}, [%4];"
                 : "=r"(r0), "=r"(r1), "=r"(r2), "=r"(r3) : "r"(addr));
}

// ---------------- generic helpers -------------------------------------------
__device__ __forceinline__ float block_sum(float v) {
    __shared__ float sh[33];
    int lane = threadIdx.x & 31, w = threadIdx.x >> 5;
    #pragma unroll
    for (int o = 16; o > 0; o >>= 1) v += __shfl_xor_sync(0xffffffffu, v, o);
    if (lane == 0) sh[w] = v;
    __syncthreads();
    if (threadIdx.x == 0) {
        float t = 0.f;
        int nw = blockDim.x >> 5;
        for (int i = 0; i < nw; i++) t += sh[i];
        sh[32] = t;
    }
    __syncthreads();
    float r = sh[32];
    __syncthreads();
    return r;
}
__device__ __forceinline__ float siluf(float x) { return x / (1.f + expf(-x)); }

// ---------------- weight prep (tf32 rounding + padding) ----------------------
__global__ void prep_w1_kernel(const float* __restrict__ w) {   // [DIP,DM] -> [DIPP,DM]
    int i4 = blockIdx.x * blockDim.x + threadIdx.x;             // float4 index
    int row = i4 >> 8;                                          // DM/4 = 256
    float4 v = make_float4(0.f, 0.f, 0.f, 0.f);
    if (row < DIP) {
        float4 s = ((const float4*)w)[i4];
        v = make_float4(rna_tf32(s.x), rna_tf32(s.y), rna_tf32(s.z), rna_tf32(s.w));
    }
    ((float4*)g_w1t)[i4] = v;
}
__global__ void prep_w2_kernel(const float* __restrict__ w) {   // [DM,DI]
    int i4 = blockIdx.x * blockDim.x + threadIdx.x;
    float4 s = ((const float4*)w)[i4];
    ((float4*)g_w2t)[i4] = make_float4(rna_tf32(s.x), rna_tf32(s.y), rna_tf32(s.z), rna_tf32(s.w));
}

// ---------------- flip permutation ------------------------------------------
__global__ void pos_kernel(const unsigned char* __restrict__ mask) {
    int b = blockIdx.x;
    float cnt = 0.f;
    for (int i = threadIdx.x; i < LSEQ; i += blockDim.x)
        cnt += (mask[b*LSEQ + i] == 0) ? 1.f : 0.f;
    float total = block_sum(cnt);
    int len = (int)(total + 0.5f);
    for (int i = threadIdx.x; i < LSEQ; i += blockDim.x)
        g_pos[b*LSEQ + i] = (i < len) ? (len - 1 - i) : i;
}

// ---------------- layernorms -------------------------------------------------
__global__ void ln_in_kernel(const float* __restrict__ in) {
    int row = blockIdx.x;
    const float* x = in + (size_t)row * DM;
    float s = 0.f, s2 = 0.f;
    for (int i = threadIdx.x; i < DM; i += blockDim.x) { float v = x[i]; s += v; s2 += v*v; }
    float sum = block_sum(s), sums = block_sum(s2);
    float mu = sum / DM, var = sums / DM - mu*mu;
    float rs = rsqrtf(var + EPSV);
    float* o = g_h + (size_t)row * DM;
    for (int i = threadIdx.x; i < DM; i += blockDim.x)
        o[i] = rna_tf32((x[i] - mu) * rs);              // tf32-rounded for GEMM1
}
__global__ void ln_out_kernel(float* __restrict__ out) {
    int row = blockIdx.x;
    const float* x = g_o + (size_t)row * DM;
    float s = 0.f, s2 = 0.f;
    for (int i = threadIdx.x; i < DM; i += blockDim.x) { float v = x[i]; s += v; s2 += v*v; }
    float sum = block_sum(s), sums = block_sum(s2);
    float mu = sum / DM, var = sums / DM - mu*mu;
    float rs = rsqrtf(var + EPSV);
    float* o = out + (size_t)row * DM;
    for (int i = threadIdx.x; i < DM; i += blockDim.x) o[i] = (x[i] - mu) * rs;
}

// ---------------- tf32 mma.sync GEMM (NT) ------------------------------------
// C[M,N] = A[M,K] * B[N,K]^T. Tile 128x128, BK=32, 8 warps (2Mx4N), warp 64x32.
// 3-stage cp.async pipeline; ldmatrix.x4.b16 reinterpreted for tf32 fragments.
#define GST 3
#define GEMM_SMEM (GST*32768 + 1024)

__device__ __forceinline__ void mma_gemm_body(const float* __restrict__ A,
                                              const float* __restrict__ B,
                                              float* __restrict__ C,
                                              int N, int K) {
    extern __shared__ char dynsmem[];
    uint32_t sbase = (smem_u32(dynsmem) + 1023) & ~1023u;

    const int tid  = threadIdx.x;
    const int warp = tid >> 5, lane = tid & 31;
    const int m0 = blockIdx.y * 128, n0 = blockIdx.x * 128;
    const int wm = (warp & 1) * 64, wn = (warp >> 1) * 32;
    const int NITER = K >> 5;

    float acc[4][4][4];
    #pragma unroll
    for (int i = 0; i < 4; i++)
        #pragma unroll
        for (int j = 0; j < 4; j++)
            #pragma unroll
            for (int k = 0; k < 4; k++) acc[i][j][k] = 0.f;

    auto issue = [&](int kc) {
        int st = kc % GST;
        uint32_t sa = sbase + st * 32768;
        uint32_t sb = sa + 16384;
        const float* Ab = A + (size_t)m0 * K + kc * 32;
        const float* Bb = B + (size_t)n0 * K + kc * 32;
        #pragma unroll
        for (int i = 0; i < 4; i++) {
            int chunk = tid + i * 256;
            int row = chunk >> 3, c4 = chunk & 7;
            uint32_t off = sw128(row * 128 + c4 * 16);
            cp16(sa + off, Ab + (size_t)row * K + c4 * 4);
            cp16(sb + off, Bb + (size_t)row * K + c4 * 4);
        }
        CP_COMMIT();
    };

    issue(0);
    issue(1);

    for (int kc = 0; kc < NITER; kc++) {
        if (kc + 2 < NITER) issue(kc + 2);
        else CP_COMMIT();
        CP_WAIT2();
        __syncthreads();

        uint32_t sa = sbase + (kc % GST) * 32768;
        uint32_t sb = sa + 16384;

        #pragma unroll
        for (int ks = 0; ks < 4; ks++) {
            int k0 = ks * 8;
            // A fragments: 4 M-tiles of 16 rows each
            uint32_t af[4][4];
            {
                int m = lane >> 3;
                int arow = (lane & 7) + ((m & 1) << 3);
                int acol = k0 + ((m & 2) ? 4 : 0);
                #pragma unroll
                for (int mt = 0; mt < 4; mt++) {
                    uint32_t addr = sa + sw128((wm + mt*16 + arow) * 128 + acol * 4);
                    ldsm4(af[mt][0], af[mt][1], af[mt][2], af[mt][3], addr);
                }
            }
            // B fragments: 4 N-tiles of 8 cols, fetched 2 tiles per ldmatrix.x4
            uint32_t bf[4][2];
            {
                int m = lane >> 3;
                int brow = (lane & 7) + ((m & 2) << 2);
                int bcol = k0 + (m & 1) * 4;
                #pragma unroll
                for (int np = 0; np < 2; np++) {
                    uint32_t addr = sb + sw128((wn + np*16 + brow) * 128 + bcol * 4);
                    ldsm4(bf[2*np][0], bf[2*np][1], bf[2*np+1][0], bf[2*np+1][1], addr);
                }
            }
            #pragma unroll
            for (int mt = 0; mt < 4; mt++)
                #pragma unroll
                for (int nt = 0; nt < 4; nt++) {
                    asm volatile(
                        "mma.sync.aligned.m16n8k8.row.col.f32.tf32.tf32.f32 "
                        "{%0,%1,%2,%3}, {%4,%5,%6,%7}, {%8,%9}, {%0,%1,%2,%3};"
                        : "+f"(acc[mt][nt][0]), "+f"(acc[mt][nt][1]),
                          "+f"(acc[mt][nt][2]), "+f"(acc[mt][nt][3])
                        : "r"(af[mt][0]), "r"(af[mt][1]), "r"(af[mt][2]), "r"(af[mt][3]),
                          "r"(bf[nt][0]), "r"(bf[nt][1]));
                }
        }
        __syncthreads();
    }

    // store C (per-fragment: rows lane/4 & +8, col pair 2*(lane%4))
    #pragma unroll
    for (int mt = 0; mt < 4; mt++) {
        #pragma unroll
        for (int nt = 0; nt < 4; nt++) {
            int r = m0 + wm + mt*16 + (lane >> 2);
            int c = n0 + wn + nt*8 + 2*(lane & 3);
            *(float2*)&C[(size_t)r * N + c]       = make_float2(acc[mt][nt][0], acc[mt][nt][1]);
            *(float2*)&C[(size_t)(r + 8) * N + c] = make_float2(acc[mt][nt][2], acc[mt][nt][3]);
        }
    }
}

__global__ void __launch_bounds__(256) mma_gemm1_kernel() {
    mma_gemm_body(g_h, g_w1t, g_zx, DIPP, DM);      // [4096,1024] x [4480,1024]^T
}
__global__ void __launch_bounds__(256) mma_gemm2_kernel() {
    mma_gemm_body(g_comb, g_w2t, g_o, DM, DI);      // [4096,2048] x [1024,2048]^T
}

// ---------------- causal depthwise conv + silu + split + dt/dA ---------------
__global__ void conv_kernel(const float* __restrict__ cw_f, const float* __restrict__ cb_f,
                            const float* __restrict__ cw_r, const float* __restrict__ cb_r,
                            const float* __restrict__ dtb_f, const float* __restrict__ Al_f,
                            const float* __restrict__ dtb_r, const float* __restrict__ Al_r) {
    int t   = blockIdx.x;
    int dir = blockIdx.y;
    int b = t / LSEQ, lp = t % LSEQ;
    const float4* cw4 = (const float4*)(dir ? cw_r : cw_f);
    const float4* cb4 = (const float4*)(dir ? cb_r : cb_f);

    int rows[4];
    #pragma unroll
    for (int k = 0; k < 4; k++) {
        int j = lp + k - 3;
        rows[k] = (j >= 0) ? (b*LSEQ + (dir ? g_pos[b*LSEQ + j] : j)) : -1;
    }

    for (int c4 = threadIdx.x; c4 < CDIM/4; c4 += blockDim.x) {
        float4 bias = cb4[c4];
        float acc[4] = {bias.x, bias.y, bias.z, bias.w};
        float4 w[4];
        #pragma unroll
        for (int j = 0; j < 4; j++) w[j] = cw4[c4*4 + j];
        #pragma unroll
        for (int k = 0; k < 4; k++) {
            if (rows[k] >= 0) {
                float4 xv = *(const float4*)(g_zx + (size_t)rows[k]*DIPP + DI + c4*4);
                acc[0] = fmaf(((const float*)&w[0])[k], xv.x, acc[0]);
                acc[1] = fmaf(((const float*)&w[1])[k], xv.y, acc[1]);
                acc[2] = fmaf(((const float*)&w[2])[k], xv.z, acc[2]);
                acc[3] = fmaf(((const float*)&w[3])[k], xv.w, acc[3]);
            }
        }
        float4 v = make_float4(siluf(acc[0]), siluf(acc[1]), siluf(acc[2]), siluf(acc[3]));
        if (c4 < DI/4)                ((float4*)(g_xc[dir] + (size_t)t*DI))[c4] = v;
        else if (c4 < (DI+DS)/4)      ((float4*)(g_Bc[dir] + (size_t)t*DS))[c4 - DI/4] = v;
        else                          ((float4*)(g_Cc[dir] + (size_t)t*DS))[c4 - (DI+DS)/4] = v;
    }

    if (threadIdx.x < NH) {
        int hh = threadIdx.x;
        int srow = b*LSEQ + (dir ? g_pos[t] : lp);
        float dtr = g_zx[(size_t)srow*DIPP + DI + CDIM + hh] + (dir ? dtb_r : dtb_f)[hh];
        float dtv = (dtr > 20.f) ? dtr : log1pf(expf(dtr));
        float A = -expf((dir ? Al_r : Al_f)[hh]);
        g_dt[dir][(size_t)t*NH + hh] = dtv;
        g_dA[dir][(size_t)t*NH + hh] = expf(dtv * A);
    }
}

// ---------------- selective scan (proven R1 scalar version) -------------------
#define CH 16
__global__ void __launch_bounds__(512) scan_kernel(const float* __restrict__ Df,
                                                   const float* __restrict__ Dr) {
    int bh  = blockIdx.x;
    int dir = blockIdx.y;
    int b = bh / NH, hd = bh % NH;
    int tid = threadIdx.x;
    int p = tid >> 3, sub = tid & 7, nb = sub * 16;
    float Dv = (dir ? Dr : Df)[hd];

    __shared__ float sB[CH][DS], sC[CH][DS], sx[CH][HD];
    __shared__ float sdt[CH], sdA[CH];

    float h[16];
    #pragma unroll
    for (int i = 0; i < 16; i++) h[i] = 0.f;

    const float* Bg  = g_Bc[dir] + (size_t)b*LSEQ*DS;
    const float* Cg  = g_Cc[dir] + (size_t)b*LSEQ*DS;
    const float* xg  = g_xc[dir] + (size_t)b*LSEQ*DI + hd*HD;
    const float* dtg = g_dt[dir] + (size_t)b*LSEQ*NH + hd;
    const float* dAg = g_dA[dir] + (size_t)b*LSEQ*NH + hd;
    float* yg        = g_y[dir]  + (size_t)b*LSEQ*DI + hd*HD;

    for (int l0 = 0; l0 < LSEQ; l0 += CH) {
        #pragma unroll
        for (int r = 0; r < 4; r++) {
            int e = r*512 + tid;
            int s = e >> 7, n = e & 127;
            sB[s][n] = Bg[(size_t)(l0+s)*DS + n];
            sC[s][n] = Cg[(size_t)(l0+s)*DS + n];
        }
        #pragma unroll
        for (int r = 0; r < 2; r++) {
            int e = r*512 + tid;
            int s = e >> 6, pp = e & 63;
            sx[s][pp] = xg[(size_t)(l0+s)*DI + pp];
        }
        if (tid < CH) {
            sdt[tid] = dtg[(size_t)(l0+tid)*NH];
            sdA[tid] = dAg[(size_t)(l0+tid)*NH];
        }
        __syncthreads();

        #pragma unroll
        for (int s = 0; s < CH; s++) {
            float xv  = sx[s][p];
            float kf  = sdt[s] * xv;
            float dAv = sdA[s];
            float yp = 0.f;
            const float4* Bv = (const float4*)&sB[s][nb];
            const float4* Cv = (const float4*)&sC[s][nb];
            #pragma unroll
            for (int q = 0; q < 4; q++) {
                float4 bq = Bv[q], cq = Cv[q];
                h[q*4+0] = fmaf(h[q*4+0], dAv, kf*bq.x); yp = fmaf(h[q*4+0], cq.x, yp);
                h[q*4+1] = fmaf(h[q*4+1], dAv, kf*bq.y); yp = fmaf(h[q*4+1], cq.y, yp);
                h[q*4+2] = fmaf(h[q*4+2], dAv, kf*bq.z); yp = fmaf(h[q*4+2], cq.z, yp);
                h[q*4+3] = fmaf(h[q*4+3], dAv, kf*bq.w); yp = fmaf(h[q*4+3], cq.w, yp);
            }
            yp += __shfl_xor_sync(0xffffffffu, yp, 1);
            yp += __shfl_xor_sync(0xffffffffu, yp, 2);
            yp += __shfl_xor_sync(0xffffffffu, yp, 4);
            if (sub == 0)
                yg[(size_t)(l0+s)*DI + p] = fmaf(Dv, xv, yp);
        }
        __syncthreads();
    }
}

// ---------------- gating + RMSNorm (in place on g_y) --------------------------
__global__ void gate_kernel(const float* __restrict__ nwf, const float* __restrict__ nwr) {
    int t = blockIdx.x, dir = blockIdx.y;
    int b = t / LSEQ, lp = t % LSEQ;
    int ztok = b*LSEQ + (dir ? g_pos[t] : lp);
    const float* nw = dir ? nwr : nwf;
    float* y = g_y[dir] + (size_t)t*DI;
    const float* z = g_zx + (size_t)ztok*DIPP;

    float gv[8];
    float s2 = 0.f;
    #pragma unroll
    for (int r = 0; r < 8; r++) {
        int c = r*256 + threadIdx.x;
        float zv = z[c];
        float g = y[c] * siluf(zv);
        gv[r] = g;
        s2 = fmaf(g, g, s2);
    }
    float total = block_sum(s2);
    float sc = rsqrtf(total / DI + EPSV);
    #pragma unroll
    for (int r = 0; r < 8; r++) {
        int c = r*256 + threadIdx.x;
        y[c] = gv[r] * sc * nw[c];
    }
}

// ---------------- combine forward + flipped reverse (tf32-rounded) ------------
__global__ void combine_kernel() {
    int t = blockIdx.x;
    int b = t / LSEQ;
    int rt = b*LSEQ + g_pos[t];
    const float* yf = g_y[0] + (size_t)t*DI;
    const float* yr = g_y[1] + (size_t)rt*DI;
    float* o = g_comb + (size_t)t*DI;
    for (int c = threadIdx.x; c < DI; c += blockDim.x)
        o[c] = rna_tf32(0.5f * (yf[c] + yr[c]));
}

// ---------------- launch -------------------------------------------------------
extern "C" void kernel_launch(void* const* d_in, const int* in_sizes, int n_in,
                              void* d_out, int out_size) {
    const float* hidden  = (const float*)d_in[0];
    const unsigned char* mask = (const unsigned char*)d_in[1];
    const float* in_proj = (const float*)d_in[2];
    const float* out_proj= (const float*)d_in[3];
    const float* cw_f  = (const float*)d_in[4];
    const float* cb_f  = (const float*)d_in[5];
    const float* dtb_f = (const float*)d_in[6];
    const float* Al_f  = (const float*)d_in[7];
    const float* D_f   = (const float*)d_in[8];
    const float* nw_f  = (const float*)d_in[9];
    const float* cw_r  = (const float*)d_in[10];
    const float* cb_r  = (const float*)d_in[11];
    const float* dtb_r = (const float*)d_in[12];
    const float* Al_r  = (const float*)d_in[13];
    const float* D_r   = (const float*)d_in[14];
    const float* nw_r  = (const float*)d_in[15];
    float* out = (float*)d_out;

    cudaFuncSetAttribute(mma_gemm1_kernel, cudaFuncAttributeMaxDynamicSharedMemorySize, GEMM_SMEM);
    cudaFuncSetAttribute(mma_gemm2_kernel, cudaFuncAttributeMaxDynamicSharedMemorySize, GEMM_SMEM);

    prep_w1_kernel<<<DIPP*DM/4/256, 256>>>(in_proj);
    prep_w2_kernel<<<DM*DI/4/256, 256>>>(out_proj);
    pos_kernel<<<BSZ, 256>>>(mask);
    ln_in_kernel<<<TOK, 256>>>(hidden);
    mma_gemm1_kernel<<<dim3(DIPP/128, TOK/128), 256, GEMM_SMEM>>>();
    conv_kernel<<<dim3(TOK, 2), 256>>>(cw_f, cb_f, cw_r, cb_r, dtb_f, Al_f, dtb_r, Al_r);
    scan_kernel<<<dim3(BSZ*NH, 2), 512>>>(D_f, D_r);
    gate_kernel<<<dim3(TOK, 2), 256>>>(nw_f, nw_r);
    combine_kernel<<<TOK, 256>>>();
    mma_gemm2_kernel<<<dim3(DM/128, TOK/128), 256, GEMM_SMEM>>>();
    ln_out_kernel<<<TOK, 256>>>(out);
}

// round 5
// speedup vs baseline: 1.3777x; 1.0369x over previous
#include <cuda_runtime.h>
#include <math.h>
#include <stdint.h>

#define DM    1024
#define DI    2048
#define HD    64
#define NH    32
#define DS    128
#define DCONV 4
#define CDIM  (DI + 2*DS)         // 2304
#define DIP   (2*DI + 2*DS + NH)  // 4384
#define DIPP  4480                // DIP padded to 128-multiple for GEMM1
#define BSZ   4
#define LSEQ  1024
#define TOK   (BSZ*LSEQ)          // 4096
#define EPSV  1e-5f

// ---------------- scratch (static device globals; no allocations) ----------
__device__ float g_h[(size_t)TOK*DM];
__device__ float g_zx[(size_t)TOK*DIPP];
__device__ float g_xc[2][(size_t)TOK*DI];
__device__ float g_Bc[2][(size_t)TOK*DS];
__device__ float g_Cc[2][(size_t)TOK*DS];
__device__ float g_dt[2][(size_t)TOK*NH];
__device__ float g_dA[2][(size_t)TOK*NH];
__device__ float g_y [2][(size_t)TOK*DI];
__device__ float g_comb[(size_t)TOK*DI];
__device__ float g_o[(size_t)TOK*DM];
__device__ int   g_pos[TOK];
__device__ float g_w1t[(size_t)DIPP*DM];
__device__ float g_w2t[(size_t)DM*DI];

// ---------------- small asm helpers -----------------------------------------
__device__ __forceinline__ uint32_t smem_u32(const void* p) {
    uint32_t a;
    asm("{ .reg .u64 t; cvta.to.shared.u64 t, %1; cvt.u32.u64 %0, t; }" : "=r"(a) : "l"(p));
    return a;
}
__device__ __forceinline__ void cp16(uint32_t dst, const void* src) {
    asm volatile("cp.async.cg.shared.global [%0], [%1], 16;" :: "r"(dst), "l"(src) : "memory");
}
#define CP_COMMIT() asm volatile("cp.async.commit_group;" ::: "memory")
#define CP_WAIT2()  asm volatile("cp.async.wait_group 2;" ::: "memory")

__device__ __forceinline__ uint32_t sw128(uint32_t off) { return off ^ ((off >> 3) & 0x70); }

__device__ __forceinline__ float rna_tf32(float x) {
    uint32_t u;
    asm("cvt.rna.tf32.f32 %0, %1;" : "=r"(u) : "f"(x));
    return __uint_as_float(u);
}

__device__ __forceinline__ void ldsm4(uint32_t& r0, uint32_t& r1, uint32_t& r2, uint32_t& r3,
                                      uint32_t addr) {
    asm volatile("ldmatrix.sync.aligned.m8n8.x4.shared.b16 {%0,%1,%2,%3}, [%4];"
                 : "=r"(r0), "=r"(r1), "=r"(r2), "=r"(r3) : "r"(addr));
}

// ---------------- generic helpers -------------------------------------------
__device__ __forceinline__ float block_sum(float v) {
    __shared__ float sh[33];
    int lane = threadIdx.x & 31, w = threadIdx.x >> 5;
    #pragma unroll
    for (int o = 16; o > 0; o >>= 1) v += __shfl_xor_sync(0xffffffffu, v, o);
    if (lane == 0) sh[w] = v;
    __syncthreads();
    if (threadIdx.x == 0) {
        float t = 0.f;
        int nw = blockDim.x >> 5;
        for (int i = 0; i < nw; i++) t += sh[i];
        sh[32] = t;
    }
    __syncthreads();
    float r = sh[32];
    __syncthreads();
    return r;
}
__device__ __forceinline__ float siluf(float x) { return x / (1.f + expf(-x)); }

// ---------------- weight prep (tf32 rounding + padding) ----------------------
__global__ void prep_w1_kernel(const float* __restrict__ w) {
    int i4 = blockIdx.x * blockDim.x + threadIdx.x;
    int row = i4 >> 8;
    float4 v = make_float4(0.f, 0.f, 0.f, 0.f);
    if (row < DIP) {
        float4 s = ((const float4*)w)[i4];
        v = make_float4(rna_tf32(s.x), rna_tf32(s.y), rna_tf32(s.z), rna_tf32(s.w));
    }
    ((float4*)g_w1t)[i4] = v;
}
__global__ void prep_w2_kernel(const float* __restrict__ w) {
    int i4 = blockIdx.x * blockDim.x + threadIdx.x;
    float4 s = ((const float4*)w)[i4];
    ((float4*)g_w2t)[i4] = make_float4(rna_tf32(s.x), rna_tf32(s.y), rna_tf32(s.z), rna_tf32(s.w));
}

// ---------------- flip permutation ------------------------------------------
__global__ void pos_kernel(const unsigned char* __restrict__ mask) {
    int b = blockIdx.x;
    float cnt = 0.f;
    for (int i = threadIdx.x; i < LSEQ; i += blockDim.x)
        cnt += (mask[b*LSEQ + i] == 0) ? 1.f : 0.f;
    float total = block_sum(cnt);
    int len = (int)(total + 0.5f);
    for (int i = threadIdx.x; i < LSEQ; i += blockDim.x)
        g_pos[b*LSEQ + i] = (i < len) ? (len - 1 - i) : i;
}

// ---------------- layernorms -------------------------------------------------
__global__ void ln_in_kernel(const float* __restrict__ in) {
    int row = blockIdx.x;
    const float* x = in + (size_t)row * DM;
    float s = 0.f, s2 = 0.f;
    for (int i = threadIdx.x; i < DM; i += blockDim.x) { float v = x[i]; s += v; s2 += v*v; }
    float sum = block_sum(s), sums = block_sum(s2);
    float mu = sum / DM, var = sums / DM - mu*mu;
    float rs = rsqrtf(var + EPSV);
    float* o = g_h + (size_t)row * DM;
    for (int i = threadIdx.x; i < DM; i += blockDim.x)
        o[i] = rna_tf32((x[i] - mu) * rs);
}
__global__ void ln_out_kernel(float* __restrict__ out) {
    int row = blockIdx.x;
    const float* x = g_o + (size_t)row * DM;
    float s = 0.f, s2 = 0.f;
    for (int i = threadIdx.x; i < DM; i += blockDim.x) { float v = x[i]; s += v; s2 += v*v; }
    float sum = block_sum(s), sums = block_sum(s2);
    float mu = sum / DM, var = sums / DM - mu*mu;
    float rs = rsqrtf(var + EPSV);
    float* o = out + (size_t)row * DM;
    for (int i = threadIdx.x; i < DM; i += blockDim.x) o[i] = (x[i] - mu) * rs;
}

// ---------------- tf32 mma.sync GEMM (NT) ------------------------------------
// C[M,N] = A[M,K] * B[N,K]^T. Tile 128x128, BK=32, 8 warps (2Mx4N), warp 64x32.
// 4-stage cp.async pipeline, issue distance 3, ONE barrier per K-iter.
#define GST 4
#define STG_BYTES 32768
#define GEMM_SMEM (GST*STG_BYTES + 1024)

__device__ __forceinline__ void mma_gemm_body(const float* __restrict__ A,
                                              const float* __restrict__ B,
                                              float* __restrict__ C,
                                              int N, int K) {
    extern __shared__ char dynsmem[];
    uint32_t sbase = (smem_u32(dynsmem) + 1023) & ~1023u;

    const int tid  = threadIdx.x;
    const int warp = tid >> 5, lane = tid & 31;
    const int m0 = blockIdx.y * 128, n0 = blockIdx.x * 128;
    const int wm = (warp & 1) * 64, wn = (warp >> 1) * 32;
    const int NITER = K >> 5;

    // per-thread cp.async addressing, hoisted (no boundary logic: inputs padded)
    const int lrow = tid >> 3, lc4 = tid & 7;
    uint32_t dst_off[4];
    const float* aptr[4];
    const float* bptr[4];
    #pragma unroll
    for (int i = 0; i < 4; i++) {
        int r = lrow + i * 32;
        dst_off[i] = sw128((uint32_t)(r * 128 + lc4 * 16));
        aptr[i] = A + (size_t)(m0 + r) * K + lc4 * 4;
        bptr[i] = B + (size_t)(n0 + r) * K + lc4 * 4;
    }

    auto issue = [&](int kc) {
        uint32_t sa = sbase + (kc & (GST - 1)) * STG_BYTES;
        uint32_t sb = sa + 16384;
        int koff = kc * 32;
        #pragma unroll
        for (int i = 0; i < 4; i++) {
            cp16(sa + dst_off[i], aptr[i] + koff);
            cp16(sb + dst_off[i], bptr[i] + koff);
        }
        CP_COMMIT();
    };

    float acc[4][4][4];
    #pragma unroll
    for (int i = 0; i < 4; i++)
        #pragma unroll
        for (int j = 0; j < 4; j++)
            #pragma unroll
            for (int k = 0; k < 4; k++) acc[i][j][k] = 0.f;

    issue(0); issue(1); issue(2);

    // fragment addressing, hoisted
    const int mq   = lane >> 3;
    const int arow = (lane & 7) + ((mq & 1) << 3);
    const int aoff = (mq & 2) ? 16 : 0;                 // bytes
    const int brow = (lane & 7) + ((mq & 2) << 2);
    const int boff = (mq & 1) * 16;                     // bytes
    int arbase[4], arx[4];
    #pragma unroll
    for (int mt = 0; mt < 4; mt++) {
        int r = wm + mt*16 + arow;
        arbase[mt] = r * 128; arx[mt] = (r & 7) << 4;
    }
    int brbase[2], brx[2];
    #pragma unroll
    for (int np = 0; np < 2; np++) {
        int r = wn + np*16 + brow;
        brbase[np] = r * 128; brx[np] = (r & 7) << 4;
    }

    for (int kc = 0; kc < NITER; kc++) {
        CP_WAIT2();
        __syncthreads();
        if (kc + 3 < NITER) issue(kc + 3);
        else CP_COMMIT();           // keep group arithmetic uniform

        uint32_t sa = sbase + (kc & (GST - 1)) * STG_BYTES;
        uint32_t sb = sa + 16384;

        #pragma unroll
        for (int ks = 0; ks < 4; ks++) {
            int kb = ks * 32;       // byte offset of this K=8 slice
            uint32_t af[4][4];
            #pragma unroll
            for (int mt = 0; mt < 4; mt++) {
                uint32_t addr = sa + arbase[mt] + (uint32_t)((kb + aoff) ^ arx[mt]);
                ldsm4(af[mt][0], af[mt][1], af[mt][2], af[mt][3], addr);
            }
            uint32_t bf[4][2];
            #pragma unroll
            for (int np = 0; np < 2; np++) {
                uint32_t addr = sb + brbase[np] + (uint32_t)((kb + boff) ^ brx[np]);
                ldsm4(bf[2*np][0], bf[2*np][1], bf[2*np+1][0], bf[2*np+1][1], addr);
            }
            #pragma unroll
            for (int mt = 0; mt < 4; mt++)
                #pragma unroll
                for (int nt = 0; nt < 4; nt++) {
                    asm volatile(
                        "mma.sync.aligned.m16n8k8.row.col.f32.tf32.tf32.f32 "
                        "{%0,%1,%2,%3}, {%4,%5,%6,%7}, {%8,%9}, {%0,%1,%2,%3};"
                        : "+f"(acc[mt][nt][0]), "+f"(acc[mt][nt][1]),
                          "+f"(acc[mt][nt][2]), "+f"(acc[mt][nt][3])
                        : "r"(af[mt][0]), "r"(af[mt][1]), "r"(af[mt][2]), "r"(af[mt][3]),
                          "r"(bf[nt][0]), "r"(bf[nt][1]));
                }
        }
    }

    #pragma unroll
    for (int mt = 0; mt < 4; mt++) {
        #pragma unroll
        for (int nt = 0; nt < 4; nt++) {
            int r = m0 + wm + mt*16 + (lane >> 2);
            int c = n0 + wn + nt*8 + 2*(lane & 3);
            *(float2*)&C[(size_t)r * N + c]       = make_float2(acc[mt][nt][0], acc[mt][nt][1]);
            *(float2*)&C[(size_t)(r + 8) * N + c] = make_float2(acc[mt][nt][2], acc[mt][nt][3]);
        }
    }
}

__global__ void __launch_bounds__(256) mma_gemm1_kernel() {
    mma_gemm_body(g_h, g_w1t, g_zx, DIPP, DM);
}
__global__ void __launch_bounds__(256) mma_gemm2_kernel() {
    mma_gemm_body(g_comb, g_w2t, g_o, DM, DI);
}

// ---------------- causal depthwise conv + silu + split + dt/dA ---------------
__global__ void conv_kernel(const float* __restrict__ cw_f, const float* __restrict__ cb_f,
                            const float* __restrict__ cw_r, const float* __restrict__ cb_r,
                            const float* __restrict__ dtb_f, const float* __restrict__ Al_f,
                            const float* __restrict__ dtb_r, const float* __restrict__ Al_r) {
    int t   = blockIdx.x;
    int dir = blockIdx.y;
    int b = t / LSEQ, lp = t % LSEQ;
    const float4* cw4 = (const float4*)(dir ? cw_r : cw_f);
    const float4* cb4 = (const float4*)(dir ? cb_r : cb_f);

    int rows[4];
    #pragma unroll
    for (int k = 0; k < 4; k++) {
        int j = lp + k - 3;
        rows[k] = (j >= 0) ? (b*LSEQ + (dir ? g_pos[b*LSEQ + j] : j)) : -1;
    }

    for (int c4 = threadIdx.x; c4 < CDIM/4; c4 += blockDim.x) {
        float4 bias = cb4[c4];
        float acc[4] = {bias.x, bias.y, bias.z, bias.w};
        float4 w[4];
        #pragma unroll
        for (int j = 0; j < 4; j++) w[j] = cw4[c4*4 + j];
        #pragma unroll
        for (int k = 0; k < 4; k++) {
            if (rows[k] >= 0) {
                float4 xv = *(const float4*)(g_zx + (size_t)rows[k]*DIPP + DI + c4*4);
                acc[0] = fmaf(((const float*)&w[0])[k], xv.x, acc[0]);
                acc[1] = fmaf(((const float*)&w[1])[k], xv.y, acc[1]);
                acc[2] = fmaf(((const float*)&w[2])[k], xv.z, acc[2]);
                acc[3] = fmaf(((const float*)&w[3])[k], xv.w, acc[3]);
            }
        }
        float4 v = make_float4(siluf(acc[0]), siluf(acc[1]), siluf(acc[2]), siluf(acc[3]));
        if (c4 < DI/4)                ((float4*)(g_xc[dir] + (size_t)t*DI))[c4] = v;
        else if (c4 < (DI+DS)/4)      ((float4*)(g_Bc[dir] + (size_t)t*DS))[c4 - DI/4] = v;
        else                          ((float4*)(g_Cc[dir] + (size_t)t*DS))[c4 - (DI+DS)/4] = v;
    }

    if (threadIdx.x < NH) {
        int hh = threadIdx.x;
        int srow = b*LSEQ + (dir ? g_pos[t] : lp);
        float dtr = g_zx[(size_t)srow*DIPP + DI + CDIM + hh] + (dir ? dtb_r : dtb_f)[hh];
        float dtv = (dtr > 20.f) ? dtr : log1pf(expf(dtr));
        float A = -expf((dir ? Al_r : Al_f)[hh]);
        g_dt[dir][(size_t)t*NH + hh] = dtv;
        g_dA[dir][(size_t)t*NH + hh] = expf(dtv * A);
    }
}

// ---------------- selective scan ----------------------------------------------
#define CH 16
__global__ void __launch_bounds__(512) scan_kernel(const float* __restrict__ Df,
                                                   const float* __restrict__ Dr) {
    int bh  = blockIdx.x;
    int dir = blockIdx.y;
    int b = bh / NH, hd = bh % NH;
    int tid = threadIdx.x;
    int p = tid >> 3, sub = tid & 7, nb = sub * 16;
    float Dv = (dir ? Dr : Df)[hd];

    __shared__ float sB[CH][DS], sC[CH][DS], sx[CH][HD];
    __shared__ float sdt[CH], sdA[CH];

    float h[16];
    #pragma unroll
    for (int i = 0; i < 16; i++) h[i] = 0.f;

    const float* Bg  = g_Bc[dir] + (size_t)b*LSEQ*DS;
    const float* Cg  = g_Cc[dir] + (size_t)b*LSEQ*DS;
    const float* xg  = g_xc[dir] + (size_t)b*LSEQ*DI + hd*HD;
    const float* dtg = g_dt[dir] + (size_t)b*LSEQ*NH + hd;
    const float* dAg = g_dA[dir] + (size_t)b*LSEQ*NH + hd;
    float* yg        = g_y[dir]  + (size_t)b*LSEQ*DI + hd*HD;

    for (int l0 = 0; l0 < LSEQ; l0 += CH) {
        #pragma unroll
        for (int r = 0; r < 4; r++) {
            int e = r*512 + tid;
            int s = e >> 7, n = e & 127;
            sB[s][n] = Bg[(size_t)(l0+s)*DS + n];
            sC[s][n] = Cg[(size_t)(l0+s)*DS + n];
        }
        #pragma unroll
        for (int r = 0; r < 2; r++) {
            int e = r*512 + tid;
            int s = e >> 6, pp = e & 63;
            sx[s][pp] = xg[(size_t)(l0+s)*DI + pp];
        }
        if (tid < CH) {
            sdt[tid] = dtg[(size_t)(l0+tid)*NH];
            sdA[tid] = dAg[(size_t)(l0+tid)*NH];
        }
        __syncthreads();

        #pragma unroll
        for (int s = 0; s < CH; s++) {
            float xv  = sx[s][p];
            float kf  = sdt[s] * xv;
            float dAv = sdA[s];
            float yp = 0.f;
            const float4* Bv = (const float4*)&sB[s][nb];
            const float4* Cv = (const float4*)&sC[s][nb];
            #pragma unroll
            for (int q = 0; q < 4; q++) {
                float4 bq = Bv[q], cq = Cv[q];
                h[q*4+0] = fmaf(h[q*4+0], dAv, kf*bq.x); yp = fmaf(h[q*4+0], cq.x, yp);
                h[q*4+1] = fmaf(h[q*4+1], dAv, kf*bq.y); yp = fmaf(h[q*4+1], cq.y, yp);
                h[q*4+2] = fmaf(h[q*4+2], dAv, kf*bq.z); yp = fmaf(h[q*4+2], cq.z, yp);
                h[q*4+3] = fmaf(h[q*4+3], dAv, kf*bq.w); yp = fmaf(h[q*4+3], cq.w, yp);
            }
            yp += __shfl_xor_sync(0xffffffffu, yp, 1);
            yp += __shfl_xor_sync(0xffffffffu, yp, 2);
            yp += __shfl_xor_sync(0xffffffffu, yp, 4);
            if (sub == 0)
                yg[(size_t)(l0+s)*DI + p] = fmaf(Dv, xv, yp);
        }
        __syncthreads();
    }
}

// ---------------- gating + RMSNorm (in place on g_y) --------------------------
__global__ void gate_kernel(const float* __restrict__ nwf, const float* __restrict__ nwr) {
    int t = blockIdx.x, dir = blockIdx.y;
    int b = t / LSEQ, lp = t % LSEQ;
    int ztok = b*LSEQ + (dir ? g_pos[t] : lp);
    const float* nw = dir ? nwr : nwf;
    float* y = g_y[dir] + (size_t)t*DI;
    const float* z = g_zx + (size_t)ztok*DIPP;

    float gv[8];
    float s2 = 0.f;
    #pragma unroll
    for (int r = 0; r < 8; r++) {
        int c = r*256 + threadIdx.x;
        float zv = z[c];
        float g = y[c] * siluf(zv);
        gv[r] = g;
        s2 = fmaf(g, g, s2);
    }
    float total = block_sum(s2);
    float sc = rsqrtf(total / DI + EPSV);
    #pragma unroll
    for (int r = 0; r < 8; r++) {
        int c = r*256 + threadIdx.x;
        y[c] = gv[r] * sc * nw[c];
    }
}

// ---------------- combine forward + flipped reverse (tf32-rounded) ------------
__global__ void combine_kernel() {
    int t = blockIdx.x;
    int b = t / LSEQ;
    int rt = b*LSEQ + g_pos[t];
    const float* yf = g_y[0] + (size_t)t*DI;
    const float* yr = g_y[1] + (size_t)rt*DI;
    float* o = g_comb + (size_t)t*DI;
    for (int c = threadIdx.x; c < DI; c += blockDim.x)
        o[c] = rna_tf32(0.5f * (yf[c] + yr[c]));
}

// ---------------- launch -------------------------------------------------------
extern "C" void kernel_launch(void* const* d_in, const int* in_sizes, int n_in,
                              void* d_out, int out_size) {
    const float* hidden  = (const float*)d_in[0];
    const unsigned char* mask = (const unsigned char*)d_in[1];
    const float* in_proj = (const float*)d_in[2];
    const float* out_proj= (const float*)d_in[3];
    const float* cw_f  = (const float*)d_in[4];
    const float* cb_f  = (const float*)d_in[5];
    const float* dtb_f = (const float*)d_in[6];
    const float* Al_f  = (const float*)d_in[7];
    const float* D_f   = (const float*)d_in[8];
    const float* nw_f  = (const float*)d_in[9];
    const float* cw_r  = (const float*)d_in[10];
    const float* cb_r  = (const float*)d_in[11];
    const float* dtb_r = (const float*)d_in[12];
    const float* Al_r  = (const float*)d_in[13];
    const float* D_r   = (const float*)d_in[14];
    const float* nw_r  = (const float*)d_in[15];
    float* out = (float*)d_out;

    cudaFuncSetAttribute(mma_gemm1_kernel, cudaFuncAttributeMaxDynamicSharedMemorySize, GEMM_SMEM);
    cudaFuncSetAttribute(mma_gemm2_kernel, cudaFuncAttributeMaxDynamicSharedMemorySize, GEMM_SMEM);

    // NOTE: launch order arranged so mma_gemm1 is launch index 3 (ncu captures it)
    prep_w1_kernel<<<DIPP*DM/4/256, 256>>>(in_proj);
    pos_kernel<<<BSZ, 256>>>(mask);
    ln_in_kernel<<<TOK, 256>>>(hidden);
    mma_gemm1_kernel<<<dim3(DIPP/128, TOK/128), 256, GEMM_SMEM>>>();
    prep_w2_kernel<<<DM*DI/4/256, 256>>>(out_proj);
    conv_kernel<<<dim3(TOK, 2), 256>>>(cw_f, cb_f, cw_r, cb_r, dtb_f, Al_f, dtb_r, Al_r);
    scan_kernel<<<dim3(BSZ*NH, 2), 512>>>(D_f, D_r);
    gate_kernel<<<dim3(TOK, 2), 256>>>(nw_f, nw_r);
    combine_kernel<<<TOK, 256>>>();
    mma_gemm2_kernel<<<dim3(DM/128, TOK/128), 256, GEMM_SMEM>>>();
    ln_out_kernel<<<TOK, 256>>>(out);
}